// round 3
// baseline (speedup 1.0000x reference)
#include <cuda_runtime.h>
#include <cuda_fp16.h>
#include <cstdint>

// ===========================================================================
// OptimizedGNNDecoder — GB300, mma.sync (HMMA) implementation.
// tcgen05 is unusable: the harness ptxas pass targets sm_103 (no 'a'),
// which rejects all arch-accelerated features. mma.sync.m16n8k16 is
// baseline PTX and hits the tensor pipe.
//
//   out[n] = [tanh(h2@Wp+bp), h2@Wv+bv],  h2 = relu(h1@W2+b2),
//   h1 = relu(nf@W1+b1),  nf = s[n] @ z[batch[n]]
//
// Trick: nf@W1 = s @ (z[g]@W1). Precompute ZW1[g] (fp16) once; per 128-node
// tile one K=64 GEMM (4 graph segments x 16 slots, zero-padded) gives the
// layer-1 pre-activations directly. batch is sorted; >=2900 nodes/graph so
// a 128-node tile spans at most 2 graphs (4 segments = huge margin).
// ===========================================================================

#define K_SLOTS 16
#define LATENT  128
#define HID     128
#define TILE_M  128
#define NGRAPH_MAX 256

__device__ __align__(16) __half g_zw1t[NGRAPH_MAX * HID * K_SLOTS]; // [g][h][k] = (z[g]@W1)[k][h]
__device__ __align__(16) __half g_w2t[HID * HID];                   // [n][k] = W2[k][n]

__device__ __forceinline__ uint32_t pack2(float lo, float hi) {
    __half2 h = __floats2half2_rn(lo, hi);
    return *reinterpret_cast<uint32_t*>(&h);
}

// m16n8k16 f16 -> f32 mma
__device__ __forceinline__ void mma16816(float c[4], const uint32_t a[4],
                                         uint32_t b0, uint32_t b1) {
    asm volatile(
        "mma.sync.aligned.m16n8k16.row.col.f32.f16.f16.f32 "
        "{%0,%1,%2,%3}, {%4,%5,%6,%7}, {%8,%9}, {%0,%1,%2,%3};"
        : "+f"(c[0]), "+f"(c[1]), "+f"(c[2]), "+f"(c[3])
        : "r"(a[0]), "r"(a[1]), "r"(a[2]), "r"(a[3]), "r"(b0), "r"(b1));
}

// ---------------- pre-kernels ----------------
// ZW1T[g][h][k] = sum_d z[g,k,d] * W1[d,h]  (fp32 accum, fp16 store)
__global__ void prep_zw1(const float* __restrict__ z, const float* __restrict__ W1) {
    __shared__ float zs[K_SLOTS * LATENT];
    const int g = blockIdx.x;
    const int h = threadIdx.x;  // 0..127
    for (int i = h; i < K_SLOTS * LATENT; i += 128)
        zs[i] = z[(size_t)g * K_SLOTS * LATENT + i];
    __syncthreads();
    float acc[K_SLOTS];
#pragma unroll
    for (int k = 0; k < K_SLOTS; k++) acc[k] = 0.f;
    for (int d = 0; d < LATENT; d++) {
        float w = __ldg(&W1[d * HID + h]);
#pragma unroll
        for (int k = 0; k < K_SLOTS; k++)
            acc[k] = fmaf(zs[k * LATENT + d], w, acc[k]);
    }
    uint32_t pk[8];
#pragma unroll
    for (int q = 0; q < 8; q++) pk[q] = pack2(acc[2 * q], acc[2 * q + 1]);
    uint4* dst = (uint4*)&g_zw1t[((size_t)g * HID + h) * K_SLOTS];
    dst[0] = make_uint4(pk[0], pk[1], pk[2], pk[3]);
    dst[1] = make_uint4(pk[4], pk[5], pk[6], pk[7]);
}

// g_w2t[n][k] = W2[k][n]
__global__ void prep_w2t(const float* __restrict__ W2) {
    const int k = blockIdx.x;
    const int n = threadIdx.x;
    g_w2t[n * HID + k] = __float2half(W2[k * HID + n]);
}

// ---------------- main fused kernel ----------------
// SMEM layout (bytes). Strides padded for conflict-free 32-bit fragment LDS.
//   AH : 128 rows x 136 half (272B/row)  — layer1 A (cols 0..63) then h1 (0..127)
//   B1 : 128 rows x  72 half (144B/row)  — [n][k] layer1 B, K=64
//   B2 : 128 rows x 136 half (272B/row)  — [n][k] W2T, K=128
static constexpr int AH_STRIDE_B = 272;
static constexpr int B1_STRIDE_B = 144;
static constexpr int B2_STRIDE_B = 272;
static constexpr int OFF_AH    = 0;                       // 34816
static constexpr int OFF_B1    = 34816;                   // 18432
static constexpr int OFF_B2    = 53248;                   // 34816
static constexpr int OFF_BIAS1 = 88064;                   // 512
static constexpr int OFF_BIAS2 = 88576;                   // 512
static constexpr int OFF_WHEAD = 89088;                   // 2048
static constexpr int SMEM_BYTES = 91136;

__global__ __launch_bounds__(128) void gnn_main(
    const float* __restrict__ s, const int* __restrict__ batch,
    const float* __restrict__ b1, const float* __restrict__ b2,
    const float* __restrict__ Wp, const float* __restrict__ bp,
    const float* __restrict__ Wv, const float* __restrict__ bv,
    float* __restrict__ out, int n_nodes, int n_graphs)
{
    extern __shared__ __align__(16) char smem[];
    const int tid  = threadIdx.x;
    const int wid  = tid >> 5;
    const int lane = tid & 31;
    const int g    = lane >> 2;   // fragment group 0..7
    const int j    = lane & 3;    // fragment lane-in-group 0..3
    const int mbase = wid * 32;   // this warp's row block
    const int tile_start = blockIdx.x * TILE_M;

    const int gf = __ldg(&batch[tile_start]);

    // ---- build A1 = S_exp [128 x 64] fp16 (row=node, 4 segments x 16 slots) ----
    {
        const int n = tile_start + tid;
        const bool valid = (n < n_nodes);
        int seg = 0;
        if (valid) {
            int gg = __ldg(&batch[n]);
            seg = gg - gf;
            if (seg > 3) seg = 3;
        }
        const float4* s4 = (const float4*)(s + (size_t)n * K_SLOTS);
        char* row = smem + OFF_AH + tid * AH_STRIDE_B;
#pragma unroll
        for (int cb = 0; cb < 8; cb++) {  // 8 x 16B covers 64 halves
            uint4 v = make_uint4(0u, 0u, 0u, 0u);
            if (valid && (cb >> 1) == seg) {
                float4 a = __ldg(&s4[(cb & 1) * 2 + 0]);
                float4 b = __ldg(&s4[(cb & 1) * 2 + 1]);
                v.x = pack2(a.x, a.y); v.y = pack2(a.z, a.w);
                v.z = pack2(b.x, b.y); v.w = pack2(b.z, b.w);
            }
            *(uint4*)(row + cb * 16) = v;
        }
    }

    // ---- build B1[n=tid][k]: 4 segments of g_zw1t[gf+sg][n][0:16] ----
    {
        char* row = smem + OFF_B1 + tid * B1_STRIDE_B;
#pragma unroll
        for (int sg = 0; sg < 4; sg++) {
            int gg = gf + sg;
            if (gg > n_graphs - 1) gg = n_graphs - 1;  // A is zero there anyway
            const uint4* src = (const uint4*)&g_zw1t[((size_t)gg * HID + tid) * K_SLOTS];
            *(uint4*)(row + sg * 32 + 0)  = src[0];
            *(uint4*)(row + sg * 32 + 16) = src[1];
        }
    }

    // ---- build B2[n=tid][k] = W2T row ----
    {
        char* row = smem + OFF_B2 + tid * B2_STRIDE_B;
        const uint4* src = (const uint4*)&g_w2t[tid * HID];
#pragma unroll
        for (int q = 0; q < 16; q++)
            *(uint4*)(row + q * 16) = src[q];
    }

    // ---- biases + head weights ----
    ((float*)(smem + OFF_BIAS1))[tid] = __ldg(&b1[tid]);
    ((float*)(smem + OFF_BIAS2))[tid] = __ldg(&b2[tid]);
    {
        float2 wp = __ldg((const float2*)(Wp + tid * 2));
        float2 wv = __ldg((const float2*)(Wv + tid * 2));
        ((float4*)(smem + OFF_WHEAD))[tid] = make_float4(wp.x, wp.y, wv.x, wv.y);
    }
    __syncthreads();

    const float* sb1 = (const float*)(smem + OFF_BIAS1);
    const float* sb2 = (const float*)(smem + OFF_BIAS2);
    const float4* swh = (const float4*)(smem + OFF_WHEAD);

    // =======================  LAYER 1 (K = 64)  =======================
    // Load the warp's full A fragments into registers (32 x u32), then the
    // AH rows are free for h1 (per-warp-private rows).
    uint32_t A1[2][4][4];
#pragma unroll
    for (int mt = 0; mt < 2; mt++) {
        const char* base0 = smem + OFF_AH + (mbase + mt * 16 + g) * AH_STRIDE_B + 4 * j;
        const char* base1 = base0 + 8 * AH_STRIDE_B;
#pragma unroll
        for (int kk = 0; kk < 4; kk++) {
            A1[mt][kk][0] = *(const uint32_t*)(base0 + kk * 32);
            A1[mt][kk][1] = *(const uint32_t*)(base1 + kk * 32);
            A1[mt][kk][2] = *(const uint32_t*)(base0 + kk * 32 + 16);
            A1[mt][kk][3] = *(const uint32_t*)(base1 + kk * 32 + 16);
        }
    }
    __syncwarp();

#pragma unroll 4
    for (int nt = 0; nt < 16; nt++) {
        float c[2][4] = {{0.f, 0.f, 0.f, 0.f}, {0.f, 0.f, 0.f, 0.f}};
        const char* bb = smem + OFF_B1 + (nt * 8 + g) * B1_STRIDE_B + 4 * j;
#pragma unroll
        for (int kk = 0; kk < 4; kk++) {
            uint32_t b0 = *(const uint32_t*)(bb + kk * 32);
            uint32_t b1r = *(const uint32_t*)(bb + kk * 32 + 16);
            mma16816(c[0], A1[0][kk], b0, b1r);
            mma16816(c[1], A1[1][kk], b0, b1r);
        }
        // epilogue1: relu(c + b1) -> fp16x2 -> h1 in AH
        const int n0 = nt * 8 + 2 * j;
        const float bia0 = sb1[n0], bia1 = sb1[n0 + 1];
#pragma unroll
        for (int mt = 0; mt < 2; mt++) {
            float x0 = fmaxf(c[mt][0] + bia0, 0.f);
            float x1 = fmaxf(c[mt][1] + bia1, 0.f);
            float x2 = fmaxf(c[mt][2] + bia0, 0.f);
            float x3 = fmaxf(c[mt][3] + bia1, 0.f);
            char* r0 = smem + OFF_AH + (mbase + mt * 16 + g) * AH_STRIDE_B + nt * 16 + 4 * j;
            *(uint32_t*)(r0)                    = pack2(x0, x1);
            *(uint32_t*)(r0 + 8 * AH_STRIDE_B)  = pack2(x2, x3);
        }
    }
    __syncwarp();

    // =======================  LAYER 2 (K = 128)  =======================
    uint32_t A2[2][8][4];
#pragma unroll
    for (int mt = 0; mt < 2; mt++) {
        const char* base0 = smem + OFF_AH + (mbase + mt * 16 + g) * AH_STRIDE_B + 4 * j;
        const char* base1 = base0 + 8 * AH_STRIDE_B;
#pragma unroll
        for (int kk = 0; kk < 8; kk++) {
            A2[mt][kk][0] = *(const uint32_t*)(base0 + kk * 32);
            A2[mt][kk][1] = *(const uint32_t*)(base1 + kk * 32);
            A2[mt][kk][2] = *(const uint32_t*)(base0 + kk * 32 + 16);
            A2[mt][kk][3] = *(const uint32_t*)(base1 + kk * 32 + 16);
        }
    }

    // head accumulators: 4 rows (32w + g + 8*ri) x 4 outputs
    float o[4][4];
#pragma unroll
    for (int ri = 0; ri < 4; ri++)
#pragma unroll
        for (int q = 0; q < 4; q++) o[ri][q] = 0.f;

#pragma unroll 4
    for (int nt = 0; nt < 16; nt++) {
        float c[2][4] = {{0.f, 0.f, 0.f, 0.f}, {0.f, 0.f, 0.f, 0.f}};
        const char* bb = smem + OFF_B2 + (nt * 8 + g) * B2_STRIDE_B + 4 * j;
#pragma unroll
        for (int kk = 0; kk < 8; kk++) {
            uint32_t b0 = *(const uint32_t*)(bb + kk * 32);
            uint32_t b1r = *(const uint32_t*)(bb + kk * 32 + 16);
            mma16816(c[0], A2[0][kk], b0, b1r);
            mma16816(c[1], A2[1][kk], b0, b1r);
        }
        // epilogue2: relu(c + b2), accumulate heads
        const int n0 = nt * 8 + 2 * j;
        const float bia0 = sb2[n0], bia1 = sb2[n0 + 1];
        const float4 w0 = swh[n0];
        const float4 w1 = swh[n0 + 1];
#pragma unroll
        for (int mt = 0; mt < 2; mt++) {
            float h00 = fmaxf(c[mt][0] + bia0, 0.f);  // row ri=2mt
            float h01 = fmaxf(c[mt][1] + bia1, 0.f);
            float h10 = fmaxf(c[mt][2] + bia0, 0.f);  // row ri=2mt+1
            float h11 = fmaxf(c[mt][3] + bia1, 0.f);
            const int r0 = 2 * mt, r1 = 2 * mt + 1;
            o[r0][0] = fmaf(h00, w0.x, o[r0][0]); o[r0][0] = fmaf(h01, w1.x, o[r0][0]);
            o[r0][1] = fmaf(h00, w0.y, o[r0][1]); o[r0][1] = fmaf(h01, w1.y, o[r0][1]);
            o[r0][2] = fmaf(h00, w0.z, o[r0][2]); o[r0][2] = fmaf(h01, w1.z, o[r0][2]);
            o[r0][3] = fmaf(h00, w0.w, o[r0][3]); o[r0][3] = fmaf(h01, w1.w, o[r0][3]);
            o[r1][0] = fmaf(h10, w0.x, o[r1][0]); o[r1][0] = fmaf(h11, w1.x, o[r1][0]);
            o[r1][1] = fmaf(h10, w0.y, o[r1][1]); o[r1][1] = fmaf(h11, w1.y, o[r1][1]);
            o[r1][2] = fmaf(h10, w0.z, o[r1][2]); o[r1][2] = fmaf(h11, w1.z, o[r1][2]);
            o[r1][3] = fmaf(h10, w0.w, o[r1][3]); o[r1][3] = fmaf(h11, w1.w, o[r1][3]);
        }
    }

    // ---- reduce head partials across the 4 lanes of each group ----
#pragma unroll
    for (int ri = 0; ri < 4; ri++)
#pragma unroll
        for (int q = 0; q < 4; q++) {
            float v = o[ri][q];
            v += __shfl_xor_sync(0xffffffffu, v, 1);
            v += __shfl_xor_sync(0xffffffffu, v, 2);
            o[ri][q] = v;
        }

    // lane j of each group writes row (32w + g + 8j)
    {
        const int row = mbase + g + 8 * j;
        const int n = tile_start + row;
        if (n < n_nodes) {
            float vbp0 = __ldg(&bp[0]), vbp1 = __ldg(&bp[1]);
            float vbv0 = __ldg(&bv[0]), vbv1 = __ldg(&bv[1]);
            float4 res = make_float4(tanhf(o[j][0] + vbp0), tanhf(o[j][1] + vbp1),
                                     o[j][2] + vbv0, o[j][3] + vbv1);
            ((float4*)out)[n] = res;
        }
    }
}

// ---------------- launch ----------------
extern "C" void kernel_launch(void* const* d_in, const int* in_sizes, int n_in,
                              void* d_out, int out_size) {
    const float* z     = (const float*)d_in[0];
    const float* s     = (const float*)d_in[1];
    const int*   batch = (const int*)d_in[2];
    const float* W1    = (const float*)d_in[3];
    const float* b1    = (const float*)d_in[4];
    const float* W2    = (const float*)d_in[5];
    const float* b2    = (const float*)d_in[6];
    const float* Wp    = (const float*)d_in[7];
    const float* bp    = (const float*)d_in[8];
    const float* Wv    = (const float*)d_in[9];
    const float* bv    = (const float*)d_in[10];

    const int n_nodes  = in_sizes[2];
    int n_graphs = in_sizes[0] / (K_SLOTS * LATENT);
    if (n_graphs > NGRAPH_MAX) n_graphs = NGRAPH_MAX;

    cudaFuncSetAttribute(gnn_main, cudaFuncAttributeMaxDynamicSharedMemorySize,
                         SMEM_BYTES);

    prep_zw1<<<n_graphs, 128>>>(z, W1);
    prep_w2t<<<HID, HID>>>(W2);

    const int tiles = (n_nodes + TILE_M - 1) / TILE_M;
    gnn_main<<<tiles, 128, SMEM_BYTES>>>(s, batch, b1, b2, Wp, bp, Wv, bv,
                                         (float*)d_out, n_nodes, n_graphs);
}

// round 5
// speedup vs baseline: 1.5117x; 1.5117x over previous
#include <cuda_runtime.h>
#include <cuda_fp16.h>
#include <cstdint>

// ===========================================================================
// OptimizedGNNDecoder — GB300, mma.sync (HMMA), persistent-CTA version.
//
//   out[n] = [tanh(h2@Wp+bp), h2@Wv+bv],  h2 = relu(h1@W2+b2),
//   h1 = relu(nf@W1+b1),  nf = s[n] @ z[batch[n]]
//
// R4 changes vs R3 (74.5us):
//  - prep_zw1 was 37.4us at occ 6%: now one merged prep kernel, 1152 CTAs
//    (per-(g,k) ZW1 slices + W2 transpose)  -> ~3us.
//  - gnn_main: persistent grid (2 CTAs/SM); W2T/biases/heads loaded into
//    smem ONCE per CTA, loop over tiles rebuilding only A1/B1 (4KB each).
// ===========================================================================

#define K_SLOTS 16
#define LATENT  128
#define HID     128
#define TILE_M  128
#define NGRAPH_MAX 256

__device__ __align__(16) __half g_zw1t[NGRAPH_MAX * HID * K_SLOTS]; // [g][h][k] = (z[g]@W1)[k][h]
__device__ __align__(16) __half g_w2t[HID * HID];                   // [n][k] = W2[k][n]

__device__ __forceinline__ uint32_t pack2(float lo, float hi) {
    __half2 h = __floats2half2_rn(lo, hi);
    return *reinterpret_cast<uint32_t*>(&h);
}

// m16n8k16 f16 -> f32 mma
__device__ __forceinline__ void mma16816(float c[4], const uint32_t a[4],
                                         uint32_t b0, uint32_t b1) {
    asm volatile(
        "mma.sync.aligned.m16n8k16.row.col.f32.f16.f16.f32 "
        "{%0,%1,%2,%3}, {%4,%5,%6,%7}, {%8,%9}, {%0,%1,%2,%3};"
        : "+f"(c[0]), "+f"(c[1]), "+f"(c[2]), "+f"(c[3])
        : "r"(a[0]), "r"(a[1]), "r"(a[2]), "r"(a[3]), "r"(b0), "r"(b1));
}

// ---------------- merged prep kernel ----------------
// blocks [0, n_graphs*16):  b -> (g = b>>4, k = b&15); thread h computes
//   ZW1T[g][h][k] = sum_d z[g,k,d] * W1[d,h]
// blocks [n_graphs*16, +128): k-column of the W2 transpose.
__global__ __launch_bounds__(128) void prep_all(
    const float* __restrict__ z, const float* __restrict__ W1,
    const float* __restrict__ W2, int n_graphs)
{
    const int b = blockIdx.x;
    const int t = threadIdx.x;
    const int nzw = n_graphs * K_SLOTS;
    if (b < nzw) {
        const int g = b >> 4, k = b & 15;
        __shared__ float zrow[LATENT];
        zrow[t] = __ldg(&z[((size_t)g * K_SLOTS + k) * LATENT + t]);
        __syncthreads();
        float a0 = 0.f, a1 = 0.f, a2 = 0.f, a3 = 0.f;
#pragma unroll
        for (int d = 0; d < LATENT; d += 4) {
            a0 = fmaf(zrow[d + 0], __ldg(&W1[(d + 0) * HID + t]), a0);
            a1 = fmaf(zrow[d + 1], __ldg(&W1[(d + 1) * HID + t]), a1);
            a2 = fmaf(zrow[d + 2], __ldg(&W1[(d + 2) * HID + t]), a2);
            a3 = fmaf(zrow[d + 3], __ldg(&W1[(d + 3) * HID + t]), a3);
        }
        g_zw1t[((size_t)g * HID + t) * K_SLOTS + k] =
            __float2half((a0 + a1) + (a2 + a3));
    } else {
        const int k = b - nzw;  // 0..127
        g_w2t[t * HID + k] = __float2half(__ldg(&W2[k * HID + t]));
    }
}

// ---------------- main fused kernel ----------------
// SMEM layout (bytes). Strides padded for conflict-free 32-bit fragment LDS.
//   AH : 128 rows x 136 half (272B/row)  — layer1 A (cols 0..63) then h1 (0..127)
//   B1 : 128 rows x  72 half (144B/row)  — [n][k] layer1 B, K=64
//   B2 : 128 rows x 136 half (272B/row)  — [n][k] W2T, K=128 (loaded once)
static constexpr int AH_STRIDE_B = 272;
static constexpr int B1_STRIDE_B = 144;
static constexpr int B2_STRIDE_B = 272;
static constexpr int OFF_AH    = 0;                       // 34816
static constexpr int OFF_B1    = 34816;                   // 18432
static constexpr int OFF_B2    = 53248;                   // 34816
static constexpr int OFF_BIAS1 = 88064;                   // 512
static constexpr int OFF_BIAS2 = 88576;                   // 512
static constexpr int OFF_WHEAD = 89088;                   // 2048
static constexpr int SMEM_BYTES = 91136;

__global__ __launch_bounds__(128) void gnn_main(
    const float* __restrict__ s, const int* __restrict__ batch,
    const float* __restrict__ b1, const float* __restrict__ b2,
    const float* __restrict__ Wp, const float* __restrict__ bp,
    const float* __restrict__ Wv, const float* __restrict__ bv,
    float* __restrict__ out, int n_nodes, int n_graphs, int n_tiles)
{
    extern __shared__ __align__(16) char smem[];
    const int tid  = threadIdx.x;
    const int wid  = tid >> 5;
    const int lane = tid & 31;
    const int g    = lane >> 2;   // fragment group 0..7
    const int j    = lane & 3;    // fragment lane-in-group 0..3
    const int mbase = wid * 32;   // this warp's row block

    // ---- one-time prologue: B2 = W2T, biases, head weights ----
    {
        char* row = smem + OFF_B2 + tid * B2_STRIDE_B;
        const uint4* src = (const uint4*)&g_w2t[tid * HID];
#pragma unroll
        for (int q = 0; q < 16; q++)
            *(uint4*)(row + q * 16) = src[q];
        ((float*)(smem + OFF_BIAS1))[tid] = __ldg(&b1[tid]);
        ((float*)(smem + OFF_BIAS2))[tid] = __ldg(&b2[tid]);
        float2 wp = __ldg((const float2*)(Wp + tid * 2));
        float2 wv = __ldg((const float2*)(Wv + tid * 2));
        ((float4*)(smem + OFF_WHEAD))[tid] = make_float4(wp.x, wp.y, wv.x, wv.y);
    }

    const float* sb1 = (const float*)(smem + OFF_BIAS1);
    const float* sb2 = (const float*)(smem + OFF_BIAS2);
    const float4* swh = (const float4*)(smem + OFF_WHEAD);
    const float vbp0 = __ldg(&bp[0]), vbp1 = __ldg(&bp[1]);
    const float vbv0 = __ldg(&bv[0]), vbv1 = __ldg(&bv[1]);

    // ---- persistent tile loop ----
    for (int tile = blockIdx.x; tile < n_tiles; tile += gridDim.x) {
        const int tile_start = tile * TILE_M;
        const int gf = __ldg(&batch[tile_start]);

        // protect B1 (read by all warps last iter) before rewriting
        __syncthreads();

        // -- build A1 = S_exp [128 x 64] fp16 (row=node, 4 seg x 16 slots) --
        {
            const int n = tile_start + tid;
            const bool valid = (n < n_nodes);
            int seg = 0;
            if (valid) {
                int gg = __ldg(&batch[n]);
                seg = gg - gf;
                if (seg > 3) seg = 3;
            }
            const float4* s4 = (const float4*)(s + (size_t)n * K_SLOTS);
            char* row = smem + OFF_AH + tid * AH_STRIDE_B;
#pragma unroll
            for (int cb = 0; cb < 8; cb++) {
                uint4 v = make_uint4(0u, 0u, 0u, 0u);
                if (valid && (cb >> 1) == seg) {
                    float4 a = __ldg(&s4[(cb & 1) * 2 + 0]);
                    float4 b = __ldg(&s4[(cb & 1) * 2 + 1]);
                    v.x = pack2(a.x, a.y); v.y = pack2(a.z, a.w);
                    v.z = pack2(b.x, b.y); v.w = pack2(b.z, b.w);
                }
                *(uint4*)(row + cb * 16) = v;
            }
        }

        // -- build B1[n=tid][k]: 4 segments of g_zw1t[gf+sg][n][0:16] --
        {
            char* row = smem + OFF_B1 + tid * B1_STRIDE_B;
#pragma unroll
            for (int sg = 0; sg < 4; sg++) {
                int gg = gf + sg;
                if (gg > n_graphs - 1) gg = n_graphs - 1;  // A is zero there
                const uint4* src =
                    (const uint4*)&g_zw1t[((size_t)gg * HID + tid) * K_SLOTS];
                *(uint4*)(row + sg * 32 + 0)  = src[0];
                *(uint4*)(row + sg * 32 + 16) = src[1];
            }
        }
        __syncthreads();

        // ===================  LAYER 1 (K = 64)  ===================
        uint32_t A1[2][4][4];
#pragma unroll
        for (int mt = 0; mt < 2; mt++) {
            const char* base0 =
                smem + OFF_AH + (mbase + mt * 16 + g) * AH_STRIDE_B + 4 * j;
            const char* base1 = base0 + 8 * AH_STRIDE_B;
#pragma unroll
            for (int kk = 0; kk < 4; kk++) {
                A1[mt][kk][0] = *(const uint32_t*)(base0 + kk * 32);
                A1[mt][kk][1] = *(const uint32_t*)(base1 + kk * 32);
                A1[mt][kk][2] = *(const uint32_t*)(base0 + kk * 32 + 16);
                A1[mt][kk][3] = *(const uint32_t*)(base1 + kk * 32 + 16);
            }
        }
        __syncwarp();

#pragma unroll 4
        for (int nt = 0; nt < 16; nt++) {
            float c[2][4] = {{0.f, 0.f, 0.f, 0.f}, {0.f, 0.f, 0.f, 0.f}};
            const char* bb = smem + OFF_B1 + (nt * 8 + g) * B1_STRIDE_B + 4 * j;
#pragma unroll
            for (int kk = 0; kk < 4; kk++) {
                uint32_t b0 = *(const uint32_t*)(bb + kk * 32);
                uint32_t b1r = *(const uint32_t*)(bb + kk * 32 + 16);
                mma16816(c[0], A1[0][kk], b0, b1r);
                mma16816(c[1], A1[1][kk], b0, b1r);
            }
            const int n0 = nt * 8 + 2 * j;
            const float bia0 = sb1[n0], bia1 = sb1[n0 + 1];
#pragma unroll
            for (int mt = 0; mt < 2; mt++) {
                float x0 = fmaxf(c[mt][0] + bia0, 0.f);
                float x1 = fmaxf(c[mt][1] + bia1, 0.f);
                float x2 = fmaxf(c[mt][2] + bia0, 0.f);
                float x3 = fmaxf(c[mt][3] + bia1, 0.f);
                char* r0 = smem + OFF_AH + (mbase + mt * 16 + g) * AH_STRIDE_B +
                           nt * 16 + 4 * j;
                *(uint32_t*)(r0)                   = pack2(x0, x1);
                *(uint32_t*)(r0 + 8 * AH_STRIDE_B) = pack2(x2, x3);
            }
        }
        __syncwarp();

        // ===================  LAYER 2 (K = 128)  ===================
        uint32_t A2[2][8][4];
#pragma unroll
        for (int mt = 0; mt < 2; mt++) {
            const char* base0 =
                smem + OFF_AH + (mbase + mt * 16 + g) * AH_STRIDE_B + 4 * j;
            const char* base1 = base0 + 8 * AH_STRIDE_B;
#pragma unroll
            for (int kk = 0; kk < 8; kk++) {
                A2[mt][kk][0] = *(const uint32_t*)(base0 + kk * 32);
                A2[mt][kk][1] = *(const uint32_t*)(base1 + kk * 32);
                A2[mt][kk][2] = *(const uint32_t*)(base0 + kk * 32 + 16);
                A2[mt][kk][3] = *(const uint32_t*)(base1 + kk * 32 + 16);
            }
        }

        float o[4][4];
#pragma unroll
        for (int ri = 0; ri < 4; ri++)
#pragma unroll
            for (int q = 0; q < 4; q++) o[ri][q] = 0.f;

#pragma unroll 4
        for (int nt = 0; nt < 16; nt++) {
            float c[2][4] = {{0.f, 0.f, 0.f, 0.f}, {0.f, 0.f, 0.f, 0.f}};
            const char* bb = smem + OFF_B2 + (nt * 8 + g) * B2_STRIDE_B + 4 * j;
#pragma unroll
            for (int kk = 0; kk < 8; kk++) {
                uint32_t b0 = *(const uint32_t*)(bb + kk * 32);
                uint32_t b1r = *(const uint32_t*)(bb + kk * 32 + 16);
                mma16816(c[0], A2[0][kk], b0, b1r);
                mma16816(c[1], A2[1][kk], b0, b1r);
            }
            const int n0 = nt * 8 + 2 * j;
            const float bia0 = sb2[n0], bia1 = sb2[n0 + 1];
            const float4 w0 = swh[n0];
            const float4 w1 = swh[n0 + 1];
#pragma unroll
            for (int mt = 0; mt < 2; mt++) {
                float h00 = fmaxf(c[mt][0] + bia0, 0.f);
                float h01 = fmaxf(c[mt][1] + bia1, 0.f);
                float h10 = fmaxf(c[mt][2] + bia0, 0.f);
                float h11 = fmaxf(c[mt][3] + bia1, 0.f);
                const int r0 = 2 * mt, r1 = 2 * mt + 1;
                o[r0][0] = fmaf(h00, w0.x, o[r0][0]); o[r0][0] = fmaf(h01, w1.x, o[r0][0]);
                o[r0][1] = fmaf(h00, w0.y, o[r0][1]); o[r0][1] = fmaf(h01, w1.y, o[r0][1]);
                o[r0][2] = fmaf(h00, w0.z, o[r0][2]); o[r0][2] = fmaf(h01, w1.z, o[r0][2]);
                o[r0][3] = fmaf(h00, w0.w, o[r0][3]); o[r0][3] = fmaf(h01, w1.w, o[r0][3]);
                o[r1][0] = fmaf(h10, w0.x, o[r1][0]); o[r1][0] = fmaf(h11, w1.x, o[r1][0]);
                o[r1][1] = fmaf(h10, w0.y, o[r1][1]); o[r1][1] = fmaf(h11, w1.y, o[r1][1]);
                o[r1][2] = fmaf(h10, w0.z, o[r1][2]); o[r1][2] = fmaf(h11, w1.z, o[r1][2]);
                o[r1][3] = fmaf(h10, w0.w, o[r1][3]); o[r1][3] = fmaf(h11, w1.w, o[r1][3]);
            }
        }

        // reduce head partials across the 4 lanes of each group
#pragma unroll
        for (int ri = 0; ri < 4; ri++)
#pragma unroll
            for (int q = 0; q < 4; q++) {
                float v = o[ri][q];
                v += __shfl_xor_sync(0xffffffffu, v, 1);
                v += __shfl_xor_sync(0xffffffffu, v, 2);
                o[ri][q] = v;
            }

        // lane j of each group writes row (32w + g + 8j)
        {
            const int row = mbase + g + 8 * j;
            const int n = tile_start + row;
            if (n < n_nodes) {
                float4 res = make_float4(tanhf(o[j][0] + vbp0),
                                         tanhf(o[j][1] + vbp1),
                                         o[j][2] + vbv0, o[j][3] + vbv1);
                ((float4*)out)[n] = res;
            }
        }
    }
}

// ---------------- launch ----------------
extern "C" void kernel_launch(void* const* d_in, const int* in_sizes, int n_in,
                              void* d_out, int out_size) {
    const float* z     = (const float*)d_in[0];
    const float* s     = (const float*)d_in[1];
    const int*   batch = (const int*)d_in[2];
    const float* W1    = (const float*)d_in[3];
    const float* b1    = (const float*)d_in[4];
    const float* W2    = (const float*)d_in[5];
    const float* b2    = (const float*)d_in[6];
    const float* Wp    = (const float*)d_in[7];
    const float* bp    = (const float*)d_in[8];
    const float* Wv    = (const float*)d_in[9];
    const float* bv    = (const float*)d_in[10];

    const int n_nodes  = in_sizes[2];
    int n_graphs = in_sizes[0] / (K_SLOTS * LATENT);
    if (n_graphs > NGRAPH_MAX) n_graphs = NGRAPH_MAX;

    cudaFuncSetAttribute(gnn_main, cudaFuncAttributeMaxDynamicSharedMemorySize,
                         SMEM_BYTES);

    prep_all<<<n_graphs * K_SLOTS + HID, 128>>>(z, W1, W2, n_graphs);

    const int n_tiles = (n_nodes + TILE_M - 1) / TILE_M;
    int grid = 148 * 2;
    if (grid > n_tiles) grid = n_tiles;
    gnn_main<<<grid, 128, SMEM_BYTES>>>(s, batch, b1, b2, Wp, bp, Wv, bv,
                                        (float*)d_out, n_nodes, n_graphs,
                                        n_tiles);
}

// round 8
// speedup vs baseline: 1.6511x; 1.0922x over previous
#include <cuda_runtime.h>
#include <cuda_fp16.h>
#include <cstdint>

// ===========================================================================
// OptimizedGNNDecoder — GB300, mma.sync (HMMA), persistent CTAs, v3.
//
//   out[n] = [tanh(h2@Wp+bp), h2@Wv+bv],  h2 = relu(h1@W2+b2),
//   h1 = relu(nf@W1+b1),  nf = s[n] @ z[batch[n]]
//
// R6 changes vs R5 (49.3us, shared-pipe-bound at 50.7%):
//  - h1 never touches smem: layer-1 C fragments are converted in registers
//    straight into layer-2 A fragments (identical lane/row mapping).
//  - Pair-permuted, XOR-swizzled operand tiles -> all fragment loads are
//    conflict-free LDS.64; no padding -> smem 91KB -> 67KB -> 3 CTAs/SM.
//  - Layer-1 K is dynamic: 32 (tile spans <=2 graphs, the ~always case)
//    or 64 (fallback).
// ===========================================================================

#define K_SLOTS 16
#define LATENT  128
#define HID     128
#define TILE_M  128
#define NGRAPH_MAX 256

__device__ __align__(16) __half g_zw1t[NGRAPH_MAX * HID * K_SLOTS]; // [g][h][k]
__device__ __align__(16) __half g_w2t[HID * HID];                   // [n][k] = W2[k][n]

__device__ __forceinline__ uint32_t pack2(float lo, float hi) {
    __half2 h = __floats2half2_rn(lo, hi);
    return *reinterpret_cast<uint32_t*>(&h);
}

// m16n8k16 f16 -> f32 mma
__device__ __forceinline__ void mma16816(float c[4], uint32_t a0, uint32_t a1,
                                         uint32_t a2, uint32_t a3,
                                         uint32_t b0, uint32_t b1) {
    asm volatile(
        "mma.sync.aligned.m16n8k16.row.col.f32.f16.f16.f32 "
        "{%0,%1,%2,%3}, {%4,%5,%6,%7}, {%8,%9}, {%0,%1,%2,%3};"
        : "+f"(c[0]), "+f"(c[1]), "+f"(c[2]), "+f"(c[3])
        : "r"(a0), "r"(a1), "r"(a2), "r"(a3), "r"(b0), "r"(b1));
}

// ---------------- merged prep kernel ----------------
__global__ __launch_bounds__(128) void prep_all(
    const float* __restrict__ z, const float* __restrict__ W1,
    const float* __restrict__ W2, int n_graphs)
{
    const int b = blockIdx.x;
    const int t = threadIdx.x;
    const int nzw = n_graphs * K_SLOTS;
    if (b < nzw) {
        const int g = b >> 4, k = b & 15;
        __shared__ float zrow[LATENT];
        zrow[t] = __ldg(&z[((size_t)g * K_SLOTS + k) * LATENT + t]);
        __syncthreads();
        float a0 = 0.f, a1 = 0.f, a2 = 0.f, a3 = 0.f;
#pragma unroll
        for (int d = 0; d < LATENT; d += 4) {
            a0 = fmaf(zrow[d + 0], __ldg(&W1[(d + 0) * HID + t]), a0);
            a1 = fmaf(zrow[d + 1], __ldg(&W1[(d + 1) * HID + t]), a1);
            a2 = fmaf(zrow[d + 2], __ldg(&W1[(d + 2) * HID + t]), a2);
            a3 = fmaf(zrow[d + 3], __ldg(&W1[(d + 3) * HID + t]), a3);
        }
        g_zw1t[((size_t)g * HID + t) * K_SLOTS + k] =
            __float2half((a0 + a1) + (a2 + a3));
    } else {
        const int k = b - nzw;  // 0..127
        g_w2t[t * HID + k] = __float2half(__ldg(&W2[k * HID + t]));
    }
}

// ---------------- smem layout ----------------
// All operand tiles pair-permuted: within each 16-K block (8 half2 words),
// word order is [w0,w4,w1,w5,w2,w6,w3,w7] so one LDS.64 yields an mma word
// pair. 16-K blocks are XOR-swizzled by row for bank-conflict freedom.
static constexpr int OFF_A1    = 0;       // 128 rows x 128B (64 half, K<=64)
static constexpr int OFF_B1    = 16384;   // 128 rows x 128B
static constexpr int OFF_B2    = 32768;   // 128 rows x 256B (128 half)
static constexpr int OFF_BIAS1 = 65536;   // 512
static constexpr int OFF_BIAS2 = 66048;   // 512
static constexpr int OFF_WHEAD = 66560;   // 2048
static constexpr int SMEM_BYTES = 68608;  // 67KB -> 3 CTAs/SM

// ---------------- per-tile body (templated on layer-1 K blocks) ----------------
template <int NBLK>
__device__ __forceinline__ void tile_body(
    char* smem, const float* __restrict__ s, const int* __restrict__ batch,
    const float* sb1, const float* sb2, const float4* swh,
    float vbp0, float vbp1, float vbv0, float vbv1,
    float* __restrict__ out, int tile_start, int gf, int n_nodes, int n_graphs,
    int tid, int wid, int g, int j, int mbase)
{
    // ---- build A1: row = node tid, NBLK 16-slot blocks, seg block = s-row ----
    {
        const int n = tile_start + tid;
        const bool valid = (n < n_nodes);
        int seg = 0;
        uint4 u0 = make_uint4(0u, 0u, 0u, 0u);
        uint4 u1 = make_uint4(0u, 0u, 0u, 0u);
        if (valid) {
            int gg = __ldg(&batch[n]);
            seg = gg - gf;
            if (seg > NBLK - 1) seg = NBLK - 1;
            const float4* s4 = (const float4*)(s + (size_t)n * K_SLOTS);
            float4 f0 = __ldg(&s4[0]), f1 = __ldg(&s4[1]);
            float4 f2 = __ldg(&s4[2]), f3 = __ldg(&s4[3]);
            uint32_t w0 = pack2(f0.x, f0.y), w1 = pack2(f0.z, f0.w);
            uint32_t w2 = pack2(f1.x, f1.y), w3 = pack2(f1.z, f1.w);
            uint32_t w4 = pack2(f2.x, f2.y), w5 = pack2(f2.z, f2.w);
            uint32_t w6 = pack2(f3.x, f3.y), w7 = pack2(f3.z, f3.w);
            u0 = make_uint4(w0, w4, w1, w5);   // pair-permute
            u1 = make_uint4(w2, w6, w3, w7);
        }
        char* row = smem + OFF_A1 + tid * 128;
#pragma unroll
        for (int kk = 0; kk < NBLK; kk++) {
            const int sw = ((kk ^ (tid & 3)) * 32);
            if (kk == seg && valid) {
                *(uint4*)(row + sw)      = u0;
                *(uint4*)(row + sw + 16) = u1;
            } else {
                *(uint4*)(row + sw)      = make_uint4(0u, 0u, 0u, 0u);
                *(uint4*)(row + sw + 16) = make_uint4(0u, 0u, 0u, 0u);
            }
        }
    }

    // ---- build B1: row = h index tid, block sg = g_zw1t[gf+sg][tid][:] ----
    {
        char* row = smem + OFF_B1 + tid * 128;
#pragma unroll
        for (int sg = 0; sg < NBLK; sg++) {
            int gg = gf + sg;
            if (gg > n_graphs - 1) gg = n_graphs - 1;  // A is zero there
            const uint4* src =
                (const uint4*)&g_zw1t[((size_t)gg * HID + tid) * K_SLOTS];
            uint4 s0 = src[0], s1 = src[1];
            const int sw = ((sg ^ (tid & 3)) * 32);
            *(uint4*)(row + sw)      = make_uint4(s0.x, s1.x, s0.y, s1.y);
            *(uint4*)(row + sw + 16) = make_uint4(s0.z, s1.z, s0.w, s1.w);
        }
    }
    __syncthreads();

    // ---- layer 1: K = NBLK*16, produce layer-2 A fragments in registers ----
    uint2 A1[2][NBLK][2];  // [mt][kk][0]:(a0,a2) row r ; [1]:(a1,a3) row r+8
#pragma unroll
    for (int mt = 0; mt < 2; mt++) {
        const char* base =
            smem + OFF_A1 + (mbase + 16 * mt + g) * 128 + 8 * j;
#pragma unroll
        for (int kk = 0; kk < NBLK; kk++) {
            const int sw = ((kk ^ (g & 3)) * 32);
            A1[mt][kk][0] = *(const uint2*)(base + sw);
            A1[mt][kk][1] = *(const uint2*)(base + sw + 8 * 128);
        }
    }

    uint32_t A2[2][8][4];  // layer-2 A fragments (a0,a1,a2,a3)
#pragma unroll
    for (int nt = 0; nt < 16; nt++) {
        float c[2][4] = {{0.f, 0.f, 0.f, 0.f}, {0.f, 0.f, 0.f, 0.f}};
        const char* bb = smem + OFF_B1 + (nt * 8 + g) * 128 + 8 * j;
#pragma unroll
        for (int kk = 0; kk < NBLK; kk++) {
            uint2 b = *(const uint2*)(bb + ((kk ^ (g & 3)) * 32));
            mma16816(c[0], A1[0][kk][0].x, A1[0][kk][1].x,
                           A1[0][kk][0].y, A1[0][kk][1].y, b.x, b.y);
            mma16816(c[1], A1[1][kk][0].x, A1[1][kk][1].x,
                           A1[1][kk][0].y, A1[1][kk][1].y, b.x, b.y);
        }
        // epilogue1: relu(c+b1) -> directly into A2 fragments
        const int n0 = nt * 8 + 2 * j;
        const float bia0 = sb1[n0], bia1 = sb1[n0 + 1];
        const int kk2 = nt >> 1;
        const int hi = (nt & 1) << 1;  // 0 -> a0/a1 ; 2 -> a2/a3
#pragma unroll
        for (int mt = 0; mt < 2; mt++) {
            float x0 = fmaxf(c[mt][0] + bia0, 0.f);
            float x1 = fmaxf(c[mt][1] + bia1, 0.f);
            float x2 = fmaxf(c[mt][2] + bia0, 0.f);
            float x3 = fmaxf(c[mt][3] + bia1, 0.f);
            A2[mt][kk2][hi + 0] = pack2(x0, x1);  // row r
            A2[mt][kk2][hi + 1] = pack2(x2, x3);  // row r+8
        }
    }

    // ---- layer 2: K = 128, heads accumulated from C fragments ----
    float o[4][4];
#pragma unroll
    for (int ri = 0; ri < 4; ri++)
#pragma unroll
        for (int q = 0; q < 4; q++) o[ri][q] = 0.f;

#pragma unroll
    for (int nt = 0; nt < 16; nt++) {
        float c[2][4] = {{0.f, 0.f, 0.f, 0.f}, {0.f, 0.f, 0.f, 0.f}};
        const char* bb = smem + OFF_B2 + (nt * 8 + g) * 256 + 8 * j;
#pragma unroll
        for (int kk = 0; kk < 8; kk++) {
            uint2 b = *(const uint2*)(bb + ((kk ^ g) * 32));
            mma16816(c[0], A2[0][kk][0], A2[0][kk][1],
                           A2[0][kk][2], A2[0][kk][3], b.x, b.y);
            mma16816(c[1], A2[1][kk][0], A2[1][kk][1],
                           A2[1][kk][2], A2[1][kk][3], b.x, b.y);
        }
        const int n0 = nt * 8 + 2 * j;
        const float bia0 = sb2[n0], bia1 = sb2[n0 + 1];
        const float4 w0 = swh[n0];
        const float4 w1 = swh[n0 + 1];
#pragma unroll
        for (int mt = 0; mt < 2; mt++) {
            float h00 = fmaxf(c[mt][0] + bia0, 0.f);
            float h01 = fmaxf(c[mt][1] + bia1, 0.f);
            float h10 = fmaxf(c[mt][2] + bia0, 0.f);
            float h11 = fmaxf(c[mt][3] + bia1, 0.f);
            const int r0 = 2 * mt, r1 = 2 * mt + 1;
            o[r0][0] = fmaf(h00, w0.x, o[r0][0]); o[r0][0] = fmaf(h01, w1.x, o[r0][0]);
            o[r0][1] = fmaf(h00, w0.y, o[r0][1]); o[r0][1] = fmaf(h01, w1.y, o[r0][1]);
            o[r0][2] = fmaf(h00, w0.z, o[r0][2]); o[r0][2] = fmaf(h01, w1.z, o[r0][2]);
            o[r0][3] = fmaf(h00, w0.w, o[r0][3]); o[r0][3] = fmaf(h01, w1.w, o[r0][3]);
            o[r1][0] = fmaf(h10, w0.x, o[r1][0]); o[r1][0] = fmaf(h11, w1.x, o[r1][0]);
            o[r1][1] = fmaf(h10, w0.y, o[r1][1]); o[r1][1] = fmaf(h11, w1.y, o[r1][1]);
            o[r1][2] = fmaf(h10, w0.z, o[r1][2]); o[r1][2] = fmaf(h11, w1.z, o[r1][2]);
            o[r1][3] = fmaf(h10, w0.w, o[r1][3]); o[r1][3] = fmaf(h11, w1.w, o[r1][3]);
        }
    }

    // reduce head partials across the 4 lanes of each group
#pragma unroll
    for (int ri = 0; ri < 4; ri++)
#pragma unroll
        for (int q = 0; q < 4; q++) {
            float v = o[ri][q];
            v += __shfl_xor_sync(0xffffffffu, v, 1);
            v += __shfl_xor_sync(0xffffffffu, v, 2);
            o[ri][q] = v;
        }

    // lane j of each group writes row (mbase + g + 8j)
    {
        const int row = mbase + g + 8 * j;
        const int n = tile_start + row;
        if (n < n_nodes) {
            float4 res = make_float4(tanhf(o[j][0] + vbp0),
                                     tanhf(o[j][1] + vbp1),
                                     o[j][2] + vbv0, o[j][3] + vbv1);
            ((float4*)out)[n] = res;
        }
    }
}

// ---------------- main fused kernel ----------------
__global__ __launch_bounds__(128, 3) void gnn_main(
    const float* __restrict__ s, const int* __restrict__ batch,
    const float* __restrict__ b1, const float* __restrict__ b2,
    const float* __restrict__ Wp, const float* __restrict__ bp,
    const float* __restrict__ Wv, const float* __restrict__ bv,
    float* __restrict__ out, int n_nodes, int n_graphs, int n_tiles)
{
    extern __shared__ __align__(16) char smem[];
    const int tid  = threadIdx.x;
    const int wid  = tid >> 5;
    const int lane = tid & 31;
    const int g    = lane >> 2;   // fragment group 0..7
    const int j    = lane & 3;    // fragment lane-in-group 0..3
    const int mbase = wid * 32;

    // ---- one-time prologue: B2 = W2T (pair-permuted, swizzled), consts ----
    {
        char* row = smem + OFF_B2 + tid * 256;
        const uint4* src = (const uint4*)&g_w2t[tid * HID];
#pragma unroll
        for (int kk = 0; kk < 8; kk++) {
            uint4 s0 = src[2 * kk], s1 = src[2 * kk + 1];
            const int sw = ((kk ^ (tid & 7)) * 32);
            *(uint4*)(row + sw)      = make_uint4(s0.x, s1.x, s0.y, s1.y);
            *(uint4*)(row + sw + 16) = make_uint4(s0.z, s1.z, s0.w, s1.w);
        }
        ((float*)(smem + OFF_BIAS1))[tid] = __ldg(&b1[tid]);
        ((float*)(smem + OFF_BIAS2))[tid] = __ldg(&b2[tid]);
        float2 wp = __ldg((const float2*)(Wp + tid * 2));
        float2 wv = __ldg((const float2*)(Wv + tid * 2));
        ((float4*)(smem + OFF_WHEAD))[tid] = make_float4(wp.x, wp.y, wv.x, wv.y);
    }

    const float* sb1 = (const float*)(smem + OFF_BIAS1);
    const float* sb2 = (const float*)(smem + OFF_BIAS2);
    const float4* swh = (const float4*)(smem + OFF_WHEAD);
    const float vbp0 = __ldg(&bp[0]), vbp1 = __ldg(&bp[1]);
    const float vbv0 = __ldg(&bv[0]), vbv1 = __ldg(&bv[1]);

    for (int tile = blockIdx.x; tile < n_tiles; tile += gridDim.x) {
        const int tile_start = tile * TILE_M;
        int last = tile_start + TILE_M - 1;
        if (last > n_nodes - 1) last = n_nodes - 1;
        const int gf = __ldg(&batch[tile_start]);
        const int gl = __ldg(&batch[last]);

        __syncthreads();  // protect A1/B1 from previous iteration's readers

        if (gl - gf <= 1) {
            tile_body<2>(smem, s, batch, sb1, sb2, swh, vbp0, vbp1, vbv0, vbv1,
                         out, tile_start, gf, n_nodes, n_graphs,
                         tid, wid, g, j, mbase);
        } else {
            tile_body<4>(smem, s, batch, sb1, sb2, swh, vbp0, vbp1, vbv0, vbv1,
                         out, tile_start, gf, n_nodes, n_graphs,
                         tid, wid, g, j, mbase);
        }
    }
}

// ---------------- launch ----------------
extern "C" void kernel_launch(void* const* d_in, const int* in_sizes, int n_in,
                              void* d_out, int out_size) {
    const float* z     = (const float*)d_in[0];
    const float* s     = (const float*)d_in[1];
    const int*   batch = (const int*)d_in[2];
    const float* W1    = (const float*)d_in[3];
    const float* b1    = (const float*)d_in[4];
    const float* W2    = (const float*)d_in[5];
    const float* b2    = (const float*)d_in[6];
    const float* Wp    = (const float*)d_in[7];
    const float* bp    = (const float*)d_in[8];
    const float* Wv    = (const float*)d_in[9];
    const float* bv    = (const float*)d_in[10];

    const int n_nodes  = in_sizes[2];
    int n_graphs = in_sizes[0] / (K_SLOTS * LATENT);
    if (n_graphs > NGRAPH_MAX) n_graphs = NGRAPH_MAX;

    cudaFuncSetAttribute(gnn_main, cudaFuncAttributeMaxDynamicSharedMemorySize,
                         SMEM_BYTES);

    prep_all<<<n_graphs * K_SLOTS + HID, 128>>>(z, W1, W2, n_graphs);

    const int n_tiles = (n_nodes + TILE_M - 1) / TILE_M;
    int grid = 148 * 3;
    if (grid > n_tiles) grid = n_tiles;
    gnn_main<<<grid, 128, SMEM_BYTES>>>(s, batch, b1, b2, Wp, bp, Wv, bv,
                                        (float*)d_out, n_nodes, n_graphs,
                                        n_tiles);
}

// round 10
// speedup vs baseline: 1.8789x; 1.1380x over previous
#include <cuda_runtime.h>
#include <cuda_fp16.h>
#include <cstdint>

// ===========================================================================
// OptimizedGNNDecoder — GB300, mma.sync (HMMA), persistent CTAs, v4.
//
//   out[n] = [tanh(h2@Wp+bp), h2@Wv+bv],  h2 = relu(h1@W2+b2),
//   h1 = relu(nf@W1+b1),  nf = s[n] @ z[batch[n]]
//
// R9 vs R8 (45.1us, still shared/latency bound):
//  - heads computed by a 3rd MMA (B fragments preloaded in registers once
//    per CTA) -> kills ~770 scalar FMA + shfl-reduce per thread-tile.
//  - biases folded into MMA accumulator init (layers 1,2 and heads).
//  - kk-paired operand layout: every fragment load is one LDS.128 covering
//    TWO K-blocks; XOR swizzles keep loads and builds conflict-free.
// ===========================================================================

#define K_SLOTS 16
#define LATENT  128
#define HID     128
#define TILE_M  128
#define NGRAPH_MAX 256

__device__ __align__(16) __half g_zw1t[NGRAPH_MAX * HID * K_SLOTS]; // [g][h][k]
__device__ __align__(16) __half g_w2t[HID * HID];                   // [n][k] = W2[k][n]

__device__ __forceinline__ uint32_t pack2(float lo, float hi) {
    __half2 h = __floats2half2_rn(lo, hi);
    return *reinterpret_cast<uint32_t*>(&h);
}

// m16n8k16 f16 -> f32 mma
__device__ __forceinline__ void mma16816(float c[4], uint32_t a0, uint32_t a1,
                                         uint32_t a2, uint32_t a3,
                                         uint32_t b0, uint32_t b1) {
    asm volatile(
        "mma.sync.aligned.m16n8k16.row.col.f32.f16.f16.f32 "
        "{%0,%1,%2,%3}, {%4,%5,%6,%7}, {%8,%9}, {%0,%1,%2,%3};"
        : "+f"(c[0]), "+f"(c[1]), "+f"(c[2]), "+f"(c[3])
        : "r"(a0), "r"(a1), "r"(a2), "r"(a3), "r"(b0), "r"(b1));
}

// ---------------- merged prep kernel ----------------
__global__ __launch_bounds__(128) void prep_all(
    const float* __restrict__ z, const float* __restrict__ W1,
    const float* __restrict__ W2, int n_graphs)
{
    const int b = blockIdx.x;
    const int t = threadIdx.x;
    const int nzw = n_graphs * K_SLOTS;
    if (b < nzw) {
        const int g = b >> 4, k = b & 15;
        __shared__ float zrow[LATENT];
        zrow[t] = __ldg(&z[((size_t)g * K_SLOTS + k) * LATENT + t]);
        __syncthreads();
        float a0 = 0.f, a1 = 0.f, a2 = 0.f, a3 = 0.f;
#pragma unroll
        for (int d = 0; d < LATENT; d += 4) {
            a0 = fmaf(zrow[d + 0], __ldg(&W1[(d + 0) * HID + t]), a0);
            a1 = fmaf(zrow[d + 1], __ldg(&W1[(d + 1) * HID + t]), a1);
            a2 = fmaf(zrow[d + 2], __ldg(&W1[(d + 2) * HID + t]), a2);
            a3 = fmaf(zrow[d + 3], __ldg(&W1[(d + 3) * HID + t]), a3);
        }
        g_zw1t[((size_t)g * HID + t) * K_SLOTS + k] =
            __float2half((a0 + a1) + (a2 + a3));
    } else {
        const int k = b - nzw;  // 0..127
        g_w2t[t * HID + k] = __float2half(__ldg(&W2[k * HID + t]));
    }
}

// ---------------- smem layout ----------------
// Operand tiles hold, per lane-slot j, uint4 = fragment words for TWO
// adjacent 16-K blocks: {w_j(kk0), w_{j+4}(kk0), w_j(kk1), w_{j+4}(kk1)}.
// A1/B1: 64B/row (NBLK=2) or 128B/row (NBLK=4). B2: 256B/row, 4 kk-pairs.
static constexpr int OFF_A1    = 0;       // up to 16KB (NBLK=4 fallback)
static constexpr int OFF_B1    = 16384;   // up to 16KB
static constexpr int OFF_B2    = 32768;   // 32KB
static constexpr int OFF_BIAS1 = 65536;   // 512
static constexpr int OFF_BIAS2 = 66048;   // 512
static constexpr int OFF_WH    = 66560;   // 8 rows x 64 words = 2KB
static constexpr int SMEM_BYTES = 68608;  // 67KB -> 3 CTAs/SM

// ---------------- per-tile body ----------------
template <int NBLK>
__device__ __forceinline__ void tile_body(
    char* smem, const float* __restrict__ s, const int* __restrict__ batch,
    const float* sb1, const float* sb2, const uint2* Bh,
    float hb0, float hb1,  // per-lane head bias (by j)
    float* __restrict__ out, int tile_start, int gf, int n_nodes, int n_graphs,
    int tid, int g, int j, int mbase)
{
    const int jb = j ^ ((g >> 1) & 3);   // slot swizzle (NBLK=2 layouts)
    const int pg = g & 3;                // B2 chunk swizzle

    // ---- build A1 (row = node tid) ----
    {
        const int n = tile_start + tid;
        const bool valid = (n < n_nodes);
        int seg = 0;
        uint32_t w[8];
#pragma unroll
        for (int q = 0; q < 8; q++) w[q] = 0u;
        if (valid) {
            int gg = __ldg(&batch[n]);
            seg = gg - gf;
            if (seg > NBLK - 1) seg = NBLK - 1;
            const float4* s4 = (const float4*)(s + (size_t)n * K_SLOTS);
            float4 f0 = __ldg(&s4[0]), f1 = __ldg(&s4[1]);
            float4 f2 = __ldg(&s4[2]), f3 = __ldg(&s4[3]);
            w[0] = pack2(f0.x, f0.y); w[1] = pack2(f0.z, f0.w);
            w[2] = pack2(f1.x, f1.y); w[3] = pack2(f1.z, f1.w);
            w[4] = pack2(f2.x, f2.y); w[5] = pack2(f2.z, f2.w);
            w[6] = pack2(f3.x, f3.y); w[7] = pack2(f3.z, f3.w);
        }
        if (NBLK == 2) {
            char* row = smem + OFF_A1 + tid * 64;
            const int js = (tid >> 1) & 3;
#pragma unroll
            for (int jj = 0; jj < 4; jj++) {
                uint4 v = (seg == 0)
                    ? make_uint4(w[jj], w[jj + 4], 0u, 0u)
                    : make_uint4(0u, 0u, w[jj], w[jj + 4]);
                *(uint4*)(row + ((jj ^ js) * 16)) = v;
            }
        } else {
            char* row = smem + OFF_A1 + tid * 128;
            const int powner = seg >> 1, sub = seg & 1;
#pragma unroll
            for (int p = 0; p < 2; p++) {
                char* chunk = row + ((p ^ (tid & 1)) * 64);
#pragma unroll
                for (int jj = 0; jj < 4; jj++) {
                    uint4 v = make_uint4(0u, 0u, 0u, 0u);
                    if (p == powner) {
                        if (sub == 0) { v.x = w[jj]; v.y = w[jj + 4]; }
                        else          { v.z = w[jj]; v.w = w[jj + 4]; }
                    }
                    *(uint4*)(chunk + jj * 16) = v;
                }
            }
        }
    }

    // ---- build B1 (row = h index tid) ----
    {
        if (NBLK == 2) {
            int g1 = gf + 1; if (g1 > n_graphs - 1) g1 = n_graphs - 1;
            const uint4* s0 = (const uint4*)&g_zw1t[((size_t)gf * HID + tid) * K_SLOTS];
            const uint4* s1 = (const uint4*)&g_zw1t[((size_t)g1 * HID + tid) * K_SLOTS];
            uint4 a0 = s0[0], b0 = s0[1], a1 = s1[0], b1v = s1[1];
            char* row = smem + OFF_B1 + tid * 64;
            const int js = (tid >> 1) & 3;
            *(uint4*)(row + ((0 ^ js) * 16)) = make_uint4(a0.x, b0.x, a1.x, b1v.x);
            *(uint4*)(row + ((1 ^ js) * 16)) = make_uint4(a0.y, b0.y, a1.y, b1v.y);
            *(uint4*)(row + ((2 ^ js) * 16)) = make_uint4(a0.z, b0.z, a1.z, b1v.z);
            *(uint4*)(row + ((3 ^ js) * 16)) = make_uint4(a0.w, b0.w, a1.w, b1v.w);
        } else {
            char* row = smem + OFF_B1 + tid * 128;
#pragma unroll
            for (int p = 0; p < 2; p++) {
                int ga = gf + 2 * p, gb = gf + 2 * p + 1;
                if (ga > n_graphs - 1) ga = n_graphs - 1;
                if (gb > n_graphs - 1) gb = n_graphs - 1;
                const uint4* s0 = (const uint4*)&g_zw1t[((size_t)ga * HID + tid) * K_SLOTS];
                const uint4* s1 = (const uint4*)&g_zw1t[((size_t)gb * HID + tid) * K_SLOTS];
                uint4 a0 = s0[0], b0 = s0[1], a1 = s1[0], b1v = s1[1];
                char* chunk = row + ((p ^ (tid & 1)) * 64);
                *(uint4*)(chunk + 0)  = make_uint4(a0.x, b0.x, a1.x, b1v.x);
                *(uint4*)(chunk + 16) = make_uint4(a0.y, b0.y, a1.y, b1v.y);
                *(uint4*)(chunk + 32) = make_uint4(a0.z, b0.z, a1.z, b1v.z);
                *(uint4*)(chunk + 48) = make_uint4(a0.w, b0.w, a1.w, b1v.w);
            }
        }
    }
    __syncthreads();

    // ---- layer-1 A fragments ----
    constexpr int NPAIR = NBLK / 2;
    uint4 A1f[2][NPAIR][2];  // [mt][pair][lo-row / hi-row]
#pragma unroll
    for (int mt = 0; mt < 2; mt++) {
        const int r = mbase + 16 * mt + g;
        if (NBLK == 2) {
            const char* base = smem + OFF_A1 + jb * 16;
            A1f[mt][0][0] = *(const uint4*)(base + r * 64);
            A1f[mt][0][1] = *(const uint4*)(base + (r + 8) * 64);
        } else {
#pragma unroll
            for (int p = 0; p < NPAIR; p++) {
                const char* base = smem + OFF_A1 + j * 16;
                A1f[mt][p][0] = *(const uint4*)(base + r * 128 + ((p ^ (r & 1)) * 64));
                A1f[mt][p][1] = *(const uint4*)(base + (r + 8) * 128 + ((p ^ (r & 1)) * 64));
            }
        }
    }

    // ---- layer 1: produce layer-2 A fragments (h1, fp16) in registers ----
    uint32_t H1[2][8][4];
#pragma unroll
    for (int nt = 0; nt < 16; nt++) {
        const int n0 = nt * 8 + 2 * j;
        const float bi0 = sb1[n0], bi1 = sb1[n0 + 1];
        float c[2][4] = {{bi0, bi1, bi0, bi1}, {bi0, bi1, bi0, bi1}};
        const int row = nt * 8 + g;
#pragma unroll
        for (int p = 0; p < NPAIR; p++) {
            uint4 b;
            if (NBLK == 2)
                b = *(const uint4*)(smem + OFF_B1 + row * 64 + jb * 16);
            else
                b = *(const uint4*)(smem + OFF_B1 + row * 128 +
                                    ((p ^ (row & 1)) * 64) + j * 16);
#pragma unroll
            for (int mt = 0; mt < 2; mt++) {
                mma16816(c[mt], A1f[mt][p][0].x, A1f[mt][p][1].x,
                                A1f[mt][p][0].y, A1f[mt][p][1].y, b.x, b.y);
                mma16816(c[mt], A1f[mt][p][0].z, A1f[mt][p][1].z,
                                A1f[mt][p][0].w, A1f[mt][p][1].w, b.z, b.w);
            }
        }
        const int kk2 = nt >> 1, hi = (nt & 1) << 1;
#pragma unroll
        for (int mt = 0; mt < 2; mt++) {
            H1[mt][kk2][hi + 0] = pack2(fmaxf(c[mt][0], 0.f), fmaxf(c[mt][1], 0.f));
            H1[mt][kk2][hi + 1] = pack2(fmaxf(c[mt][2], 0.f), fmaxf(c[mt][3], 0.f));
        }
    }

    // ---- layer 2 + incremental head MMA ----
    float ch[2][4] = {{hb0, hb1, hb0, hb1}, {hb0, hb1, hb0, hb1}};
    uint32_t H2[2][4];  // h2 fragments for current kk-pair
#pragma unroll
    for (int nt = 0; nt < 16; nt++) {
        const int n0 = nt * 8 + 2 * j;
        const float bi0 = sb2[n0], bi1 = sb2[n0 + 1];
        float c[2][4] = {{bi0, bi1, bi0, bi1}, {bi0, bi1, bi0, bi1}};
        const int row = nt * 8 + g;
        const char* bb = smem + OFF_B2 + row * 256 + j * 16;
#pragma unroll
        for (int p = 0; p < 4; p++) {
            uint4 b = *(const uint4*)(bb + ((p ^ pg) * 64));
#pragma unroll
            for (int mt = 0; mt < 2; mt++) {
                mma16816(c[mt], H1[mt][2 * p][0], H1[mt][2 * p][1],
                                H1[mt][2 * p][2], H1[mt][2 * p][3], b.x, b.y);
                mma16816(c[mt], H1[mt][2 * p + 1][0], H1[mt][2 * p + 1][1],
                                H1[mt][2 * p + 1][2], H1[mt][2 * p + 1][3], b.z, b.w);
            }
        }
        const int hi = (nt & 1) << 1;
#pragma unroll
        for (int mt = 0; mt < 2; mt++) {
            H2[mt][hi + 0] = pack2(fmaxf(c[mt][0], 0.f), fmaxf(c[mt][1], 0.f));
            H2[mt][hi + 1] = pack2(fmaxf(c[mt][2], 0.f), fmaxf(c[mt][3], 0.f));
        }
        if (nt & 1) {
            const int kk2 = nt >> 1;
#pragma unroll
            for (int mt = 0; mt < 2; mt++)
                mma16816(ch[mt], H2[mt][0], H2[mt][1], H2[mt][2], H2[mt][3],
                         Bh[kk2].x, Bh[kk2].y);
        }
    }

    // ---- write out: lane (g, j=0) combines with lane (g, j=1)'s vel cols ----
#pragma unroll
    for (int mt = 0; mt < 2; mt++) {
        const int src = ((g << 2) | 1);
        float v0 = __shfl_sync(0xffffffffu, ch[mt][0], src);
        float v1 = __shfl_sync(0xffffffffu, ch[mt][1], src);
        float v2 = __shfl_sync(0xffffffffu, ch[mt][2], src);
        float v3 = __shfl_sync(0xffffffffu, ch[mt][3], src);
        if (j == 0) {
            const int r = mbase + 16 * mt + g;
            const int n = tile_start + r;
            if (n < n_nodes)
                ((float4*)out)[n] =
                    make_float4(tanhf(ch[mt][0]), tanhf(ch[mt][1]), v0, v1);
            if (n + 8 < n_nodes)
                ((float4*)out)[n + 8] =
                    make_float4(tanhf(ch[mt][2]), tanhf(ch[mt][3]), v2, v3);
        }
    }
}

// ---------------- main fused kernel ----------------
__global__ __launch_bounds__(128, 3) void gnn_main(
    const float* __restrict__ s, const int* __restrict__ batch,
    const float* __restrict__ b1, const float* __restrict__ b2,
    const float* __restrict__ Wp, const float* __restrict__ bp,
    const float* __restrict__ Wv, const float* __restrict__ bv,
    float* __restrict__ out, int n_nodes, int n_graphs, int n_tiles)
{
    extern __shared__ __align__(16) char smem[];
    const int tid  = threadIdx.x;
    const int wid  = tid >> 5;
    const int lane = tid & 31;
    const int g    = lane >> 2;
    const int j    = lane & 3;
    const int mbase = wid * 32;

    // ---- one-time prologue ----
    {
        // B2 = W2T kk-paired: row tid, 4 pairs, chunk swizzle (p ^ (tid&3))
        uint32_t sw[64];
        const uint4* src = (const uint4*)&g_w2t[tid * HID];
#pragma unroll
        for (int q = 0; q < 16; q++) ((uint4*)sw)[q] = src[q];
        char* row = smem + OFF_B2 + tid * 256;
#pragma unroll
        for (int p = 0; p < 4; p++) {
            char* chunk = row + ((p ^ (tid & 3)) * 64);
#pragma unroll
            for (int jj = 0; jj < 4; jj++)
                *(uint4*)(chunk + jj * 16) =
                    make_uint4(sw[16 * p + jj], sw[16 * p + jj + 4],
                               sw[16 * p + 8 + jj], sw[16 * p + 8 + jj + 4]);
        }
        ((float*)(smem + OFF_BIAS1))[tid] = __ldg(&b1[tid]);
        ((float*)(smem + OFF_BIAS2))[tid] = __ldg(&b2[tid]);
        // head matrix Wh[q][k]: q=0,1 -> Wp[:,q]; q=2,3 -> Wv[:,q-2]; q>=4 -> 0
        uint32_t* whw = (uint32_t*)(smem + OFF_WH);
        for (int i = tid; i < 8 * 64; i += 128) {
            const int q = i >> 6, wi = i & 63;
            float lo = 0.f, hiv = 0.f;
            if (q < 2)      { lo = __ldg(&Wp[(2 * wi) * 2 + q]);
                              hiv = __ldg(&Wp[(2 * wi + 1) * 2 + q]); }
            else if (q < 4) { lo = __ldg(&Wv[(2 * wi) * 2 + q - 2]);
                              hiv = __ldg(&Wv[(2 * wi + 1) * 2 + q - 2]); }
            whw[i] = pack2(lo, hiv);
        }
    }
    __syncthreads();

    // head B fragments (persist in registers for the whole CTA lifetime)
    uint2 Bh[8];
    {
        const uint32_t* whw = (const uint32_t*)(smem + OFF_WH);
#pragma unroll
        for (int kk = 0; kk < 8; kk++) {
            Bh[kk].x = whw[g * 64 + 8 * kk + j];
            Bh[kk].y = whw[g * 64 + 8 * kk + j + 4];
        }
    }
    // per-lane head bias for accumulator init
    float hb0 = 0.f, hb1 = 0.f;
    if (j == 0) { hb0 = __ldg(&bp[0]); hb1 = __ldg(&bp[1]); }
    else if (j == 1) { hb0 = __ldg(&bv[0]); hb1 = __ldg(&bv[1]); }

    const float* sb1 = (const float*)(smem + OFF_BIAS1);
    const float* sb2 = (const float*)(smem + OFF_BIAS2);

    for (int tile = blockIdx.x; tile < n_tiles; tile += gridDim.x) {
        const int tile_start = tile * TILE_M;
        int last = tile_start + TILE_M - 1;
        if (last > n_nodes - 1) last = n_nodes - 1;
        const int gf = __ldg(&batch[tile_start]);
        const int gl = __ldg(&batch[last]);

        __syncthreads();  // protect A1/B1 from previous iteration's readers

        if (gl - gf <= 1)
            tile_body<2>(smem, s, batch, sb1, sb2, Bh, hb0, hb1, out,
                         tile_start, gf, n_nodes, n_graphs, tid, g, j, mbase);
        else
            tile_body<4>(smem, s, batch, sb1, sb2, Bh, hb0, hb1, out,
                         tile_start, gf, n_nodes, n_graphs, tid, g, j, mbase);
    }
}

// ---------------- launch ----------------
extern "C" void kernel_launch(void* const* d_in, const int* in_sizes, int n_in,
                              void* d_out, int out_size) {
    const float* z     = (const float*)d_in[0];
    const float* s     = (const float*)d_in[1];
    const int*   batch = (const int*)d_in[2];
    const float* W1    = (const float*)d_in[3];
    const float* b1    = (const float*)d_in[4];
    const float* W2    = (const float*)d_in[5];
    const float* b2    = (const float*)d_in[6];
    const float* Wp    = (const float*)d_in[7];
    const float* bp    = (const float*)d_in[8];
    const float* Wv    = (const float*)d_in[9];
    const float* bv    = (const float*)d_in[10];

    const int n_nodes  = in_sizes[2];
    int n_graphs = in_sizes[0] / (K_SLOTS * LATENT);
    if (n_graphs > NGRAPH_MAX) n_graphs = NGRAPH_MAX;

    cudaFuncSetAttribute(gnn_main, cudaFuncAttributeMaxDynamicSharedMemorySize,
                         SMEM_BYTES);

    prep_all<<<n_graphs * K_SLOTS + HID, 128>>>(z, W1, W2, n_graphs);

    const int n_tiles = (n_nodes + TILE_M - 1) / TILE_M;
    int grid = 148 * 3;
    if (grid > n_tiles) grid = n_tiles;
    gnn_main<<<grid, 128, SMEM_BYTES>>>(s, batch, b1, b2, Wp, bp, Wv, bv,
                                        (float*)d_out, n_nodes, n_graphs,
                                        n_tiles);
}